// round 5
// baseline (speedup 1.0000x reference)
#include <cuda_runtime.h>
#include <cuda_bf16.h>
#include <stdint.h>

// ---------------------------------------------------------------------------
// Exact Chamfer via uniform-grid NN, v3.
//   Grid G=32 (cell 0.25 over [-4,4]^3): ~16 pts in densest central cells.
//   hist (128 CTAs, global atomics) -> prefix (2 CTAs, one per array) ->
//   scatter (128 CTAs) -> query (4-lane quad per query, 131072 threads) ->
//   reduce (fixed-order, double; re-zeros hist for graph replay).
//   Query: Chebyshev shell walk, exact box-distance pruning (edge cells
//   extend to infinity for clamped outliers), shell lower bound
//   ((r-1)*cell)^2, quad-shared best after each shell. Exact & deterministic.
// ---------------------------------------------------------------------------

#define NPTS   16384
#define G      32
#define NC     (G*G*G)          // 32768 cells per array
#define CELLF  0.25f
#define GMINF  (-4.0f)
#define INVC   4.0f

__device__ int    g_cnt[2][NC];       // zero at load; re-zeroed by reduce
__device__ int    g_cur[2][NC];
__device__ int2   g_meta[2][NC];      // (flat offset into g_pts, count)
__device__ float4 g_pts[2 * NPTS];    // cell-sorted; w = orig index
__device__ float  g_dmin[2 * NPTS];

__device__ __forceinline__ int cell_of(float v) {
    int c = (int)floorf((v - GMINF) * INVC);
    return min(G - 1, max(0, c));
}

__global__ __launch_bounds__(256)
void hist_kernel(const float* __restrict__ pa, const float* __restrict__ pb) {
    const int t = blockIdx.x * 256 + threadIdx.x;   // 0..32767
    const int arr = t >> 14, i = t & (NPTS - 1);
    const float* s = arr ? pb : pa;
    const int ci = (cell_of(s[3 * i + 2]) * G + cell_of(s[3 * i + 1])) * G
                   + cell_of(s[3 * i + 0]);
    atomicAdd(&g_cnt[arr][ci], 1);
}

__global__ __launch_bounds__(1024)
void prefix_kernel() {    // blockIdx.x = array; each array scans its 32768 cells
    __shared__ int sc[1024];
    const int arr = blockIdx.x, tid = threadIdx.x;
    const int4* __restrict__ src = (const int4*)&g_cnt[arr][0];
    int c[32], tot = 0;
    #pragma unroll
    for (int k = 0; k < 8; ++k) {
        const int4 v = src[tid * 8 + k];
        c[4 * k + 0] = v.x; c[4 * k + 1] = v.y;
        c[4 * k + 2] = v.z; c[4 * k + 3] = v.w;
        tot += v.x + v.y + v.z + v.w;
    }
    sc[tid] = tot;
    __syncthreads();
    for (int off = 1; off < 1024; off <<= 1) {      // Hillis-Steele inclusive
        int v = sc[tid];
        int add = (tid >= off) ? sc[tid - off] : 0;
        __syncthreads();
        sc[tid] = v + add;
        __syncthreads();
    }
    int run = arr * NPTS + sc[tid] - tot;           // arr1 points start at 16384
    const int base = tid * 32;
    #pragma unroll
    for (int k = 0; k < 32; ++k) {
        g_meta[arr][base + k] = make_int2(run, c[k]);
        g_cur[arr][base + k]  = run;
        run += c[k];
    }
}

__global__ __launch_bounds__(256)
void scatter_kernel(const float* __restrict__ pa, const float* __restrict__ pb) {
    const int t = blockIdx.x * 256 + threadIdx.x;
    const int arr = t >> 14, i = t & (NPTS - 1);
    const float* s = arr ? pb : pa;
    const float x = s[3 * i + 0], y = s[3 * i + 1], z = s[3 * i + 2];
    const int ci = (cell_of(z) * G + cell_of(y)) * G + cell_of(x);
    const int pos = atomicAdd(&g_cur[arr][ci], 1);
    g_pts[pos] = make_float4(x, y, z, __int_as_float(i));
}

__global__ __launch_bounds__(256)
void query_kernel() {
    const int t   = blockIdx.x * 256 + threadIdx.x;   // 0..131071
    const int qid = t >> 2;                           // 0..32767, cell-sorted
    const int sub = t & 3;
    const int arr = qid >> 14;
    const float4 q = g_pts[qid];                      // broadcast within quad
    const float qx = q.x, qy = q.y, qz = q.z;
    const int2* __restrict__ meta = &g_meta[1 - arr][0];
    const int cx = cell_of(qx), cy = cell_of(qy), cz = cell_of(qz);

    float best = 3e38f;        // quad-shared after each shell; lane-improved within

    for (int r = 0; r < G; ++r) {
        if (r >= 1) {
            const float lb = (float)(r - 1) * CELLF;
            if (lb * lb >= best) break;               // uniform across quad
        }
        const int x0 = max(cx - r, 0), x1 = min(cx + r, G - 1);
        const int y0 = max(cy - r, 0), y1 = min(cy + r, G - 1);
        const int z0 = max(cz - r, 0), z1 = min(cz + r, G - 1);

        for (int Z = z0; Z <= z1; ++Z) {
            const int az = (Z > cz) ? (Z - cz) : (cz - Z);
            float lo = GMINF + Z * CELLF, hi = lo + CELLF;
            float bz = 0.f;
            if (qz < lo) { if (Z > 0) bz = lo - qz; }
            else if (qz > hi) { if (Z < G - 1) bz = qz - hi; }
            const float bz2 = bz * bz;
            if (bz2 >= best) continue;

            for (int Y = y0; Y <= y1; ++Y) {
                const int ay = (Y > cy) ? (Y - cy) : (cy - Y);
                const bool inner_yz = (az < r) && (ay < r);
                lo = GMINF + Y * CELLF; hi = lo + CELLF;
                float by = 0.f;
                if (qy < lo) { if (Y > 0) by = lo - qy; }
                else if (qy > hi) { if (Y < G - 1) by = qy - hi; }
                const float byz2 = fmaf(by, by, bz2);
                if (byz2 >= best) continue;

                for (int X = x0; X <= x1; ++X) {
                    const int ax = (X > cx) ? (X - cx) : (cx - X);
                    if (inner_yz && ax < r) continue;    // done at smaller r
                    lo = GMINF + X * CELLF; hi = lo + CELLF;
                    float bx = 0.f;
                    if (qx < lo) { if (X > 0) bx = lo - qx; }
                    else if (qx > hi) { if (X < G - 1) bx = qx - hi; }
                    if (fmaf(bx, bx, byz2) >= best) continue;

                    const int2 mc = __ldg(&meta[(Z * G + Y) * G + X]);
                    const int e0 = mc.x + mc.y;
                    for (int u = mc.x + sub; u < e0; u += 4) {
                        const float4 p = __ldg(&g_pts[u]);
                        const float dx = qx - p.x;
                        const float dy = qy - p.y;
                        const float dz = qz - p.z;
                        best = fminf(best, fmaf(dx, dx, fmaf(dy, dy, dz * dz)));
                    }
                }
            }
        }
        // quad-reduce: shells must agree on break/prune bound
        best = fminf(best, __shfl_xor_sync(0xffffffffu, best, 1));
        best = fminf(best, __shfl_xor_sync(0xffffffffu, best, 2));
    }
    if (sub == 0) g_dmin[arr * NPTS + __float_as_int(q.w)] = best;
}

__global__ void reduce_kernel(float* __restrict__ out) {
    __shared__ double sm[1024];
    const int tid = threadIdx.x;
    double acc = 0.0;
    for (int i = tid; i < 2 * NPTS; i += 1024)
        acc += (double)g_dmin[i];
    sm[tid] = acc;
    __syncthreads();
    for (int o = 512; o; o >>= 1) {
        if (tid < o) sm[tid] += sm[tid + o];
        __syncthreads();
    }
    if (tid == 0) out[0] = (float)(sm[0] * (1.0 / (double)NPTS));
    // re-zero histogram for next graph replay
    int* c = &g_cnt[0][0];
    for (int i = tid; i < 2 * NC; i += 1024) c[i] = 0;
}

extern "C" void kernel_launch(void* const* d_in, const int* in_sizes, int n_in,
                              void* d_out, int out_size) {
    const float* p_hat = (const float*)d_in[0];  // [16384,3]
    const float* p     = (const float*)d_in[1];  // [16384,3]
    float* out = (float*)d_out;

    hist_kernel<<<128, 256>>>(p_hat, p);
    prefix_kernel<<<2, 1024>>>();
    scatter_kernel<<<128, 256>>>(p_hat, p);
    query_kernel<<<512, 256>>>();
    reduce_kernel<<<1, 1024>>>(out);
}

// round 6
// speedup vs baseline: 2.4571x; 2.4571x over previous
#include <cuda_runtime.h>
#include <cuda_bf16.h>
#include <stdint.h>

// ---------------------------------------------------------------------------
// Exact Chamfer via uniform-grid NN, v4: WARP per query, warp-parallel walk.
//   G=32 (cell 0.25 over [-4,4]^3, ~16 pts in densest cells).
//   Per shell r: enumerate the clamped (2r+1)^3 cube 32 cells/ballot-pass
//   (lanes: Chebyshev==r filter, count>0, exact box-dist < cur). Survivors
//   scanned warp-collectively (lane-strided points), cur warp-min'ed after
//   each cell. Shell break: ((r-1)*cell)^2 >= cur. Edge cells extend to
//   infinity (clamped coords exact). fp-min order-independent -> bitwise
//   deterministic; fixed-order double reduce.
// ---------------------------------------------------------------------------

#define NPTS   16384
#define G      32
#define NC     (G*G*G)
#define CELLF  0.25f
#define GMINF  (-4.0f)
#define INVC   4.0f

__device__ int    g_cnt[2][NC];       // zero at load; re-zeroed by prefix
__device__ int    g_cur[2][NC];
__device__ int2   g_meta[2][NC];      // (flat offset into g_pts, count)
__device__ float4 g_pts[2 * NPTS];    // cell-sorted; w = orig index
__device__ float  g_dmin[2 * NPTS];

__device__ __forceinline__ int cell_of(float v) {
    int c = (int)floorf((v - GMINF) * INVC);
    return min(G - 1, max(0, c));
}

__global__ __launch_bounds__(1024)
void hist_kernel(const float* __restrict__ pa, const float* __restrict__ pb) {
    const int t = blockIdx.x * 1024 + threadIdx.x;   // 0..32767
    const int arr = t >> 14, i = t & (NPTS - 1);
    const float* s = arr ? pb : pa;
    const int ci = (cell_of(s[3 * i + 2]) * G + cell_of(s[3 * i + 1])) * G
                   + cell_of(s[3 * i + 0]);
    atomicAdd(&g_cnt[arr][ci], 1);
}

__global__ __launch_bounds__(1024)
void prefix_kernel() {    // blockIdx.x = array
    __shared__ int sc[1024];
    const int arr = blockIdx.x, tid = threadIdx.x;
    int4* __restrict__ src = (int4*)&g_cnt[arr][0];
    int c[32], tot = 0;
    #pragma unroll
    for (int k = 0; k < 8; ++k) {
        const int4 v = src[tid * 8 + k];
        c[4 * k + 0] = v.x; c[4 * k + 1] = v.y;
        c[4 * k + 2] = v.z; c[4 * k + 3] = v.w;
        tot += v.x + v.y + v.z + v.w;
    }
    sc[tid] = tot;
    __syncthreads();
    for (int off = 1; off < 1024; off <<= 1) {
        int v = sc[tid];
        int add = (tid >= off) ? sc[tid - off] : 0;
        __syncthreads();
        sc[tid] = v + add;
        __syncthreads();
    }
    int run = arr * NPTS + sc[tid] - tot;            // arr1 starts at 16384
    const int base = tid * 32;
    #pragma unroll
    for (int k = 0; k < 32; ++k) {
        g_meta[arr][base + k] = make_int2(run, c[k]);
        g_cur[arr][base + k]  = run;
        run += c[k];
    }
    // g_cnt consumed -> re-zero for next graph replay
    const int4 z = make_int4(0, 0, 0, 0);
    #pragma unroll
    for (int k = 0; k < 8; ++k) src[tid * 8 + k] = z;
}

__global__ __launch_bounds__(1024)
void scatter_kernel(const float* __restrict__ pa, const float* __restrict__ pb) {
    const int t = blockIdx.x * 1024 + threadIdx.x;
    const int arr = t >> 14, i = t & (NPTS - 1);
    const float* s = arr ? pb : pa;
    const float x = s[3 * i + 0], y = s[3 * i + 1], z = s[3 * i + 2];
    const int ci = (cell_of(z) * G + cell_of(y)) * G + cell_of(x);
    const int pos = atomicAdd(&g_cur[arr][ci], 1);
    g_pts[pos] = make_float4(x, y, z, __int_as_float(i));
}

__device__ __forceinline__ float axis_bd(float q, int X) {
    const float lo = GMINF + X * CELLF, hi = lo + CELLF;
    float b = 0.f;
    if (q < lo)      { if (X > 0)     b = lo - q; }
    else if (q > hi) { if (X < G - 1) b = q - hi; }
    return b;
}

__global__ __launch_bounds__(256)
void query_kernel() {
    const int w    = blockIdx.x * 8 + (threadIdx.x >> 5);   // 0..32767
    const int lane = threadIdx.x & 31;
    const int arr  = w >> 14;
    const float4 q = g_pts[w];                   // broadcast load
    const float qx = q.x, qy = q.y, qz = q.z;
    const int2* __restrict__ meta = &g_meta[1 - arr][0];
    const int cx = cell_of(qx), cy = cell_of(qy), cz = cell_of(qz);

    float cur = 3e38f;                           // warp-uniform

    for (int r = 0; r < G; ++r) {
        if (r >= 1) {
            const float lb = (float)(r - 1) * CELLF;
            if (lb * lb >= cur) break;
        }
        const int x0 = max(cx - r, 0), x1 = min(cx + r, G - 1);
        const int y0 = max(cy - r, 0), y1 = min(cy + r, G - 1);
        const int z0 = max(cz - r, 0), z1 = min(cz + r, G - 1);
        const int nx = x1 - x0 + 1, ny = y1 - y0 + 1, nz = z1 - z0 + 1;
        const int tot = nx * ny * nz;

        for (int basei = 0; basei < tot; basei += 32) {
            const int idx = basei + lane;
            bool  alive = false;
            float bd2 = 0.f;
            int   off = 0, cnt = 0;
            if (idx < tot) {
                const int X = x0 + idx % nx;
                const int rem = idx / nx;
                const int Y = y0 + rem % ny;
                const int Z = z0 + rem / ny;
                const int chb = max(abs(X - cx), max(abs(Y - cy), abs(Z - cz)));
                if (chb == r) {                          // shell only
                    const int2 mc = __ldg(&meta[(Z * G + Y) * G + X]);
                    off = mc.x; cnt = mc.y;
                    if (cnt > 0) {
                        const float bx = axis_bd(qx, X);
                        const float by = axis_bd(qy, Y);
                        const float bz = axis_bd(qz, Z);
                        bd2 = fmaf(bx, bx, fmaf(by, by, bz * bz));
                        alive = (bd2 < cur);
                    }
                }
            }
            unsigned mask = __ballot_sync(0xffffffffu, alive);
            while (mask) {
                const int s = __ffs(mask) - 1;
                mask &= mask - 1;
                const float bd2s = __shfl_sync(0xffffffffu, bd2, s);
                if (bd2s >= cur) continue;               // improved-cur prune
                const int offs = __shfl_sync(0xffffffffu, off, s);
                const int cnts = __shfl_sync(0xffffffffu, cnt, s);
                float lm = 3e38f;
                for (int u = offs + lane; u < offs + cnts; u += 32) {
                    const float4 p = __ldg(&g_pts[u]);
                    const float dx = qx - p.x;
                    const float dy = qy - p.y;
                    const float dz = qz - p.z;
                    lm = fminf(lm, fmaf(dx, dx, fmaf(dy, dy, dz * dz)));
                }
                #pragma unroll
                for (int o = 16; o; o >>= 1)
                    lm = fminf(lm, __shfl_xor_sync(0xffffffffu, lm, o));
                cur = fminf(cur, lm);                    // stays warp-uniform
            }
        }
    }
    if (lane == 0) g_dmin[arr * NPTS + __float_as_int(q.w)] = cur;
}

__global__ void reduce_kernel(float* __restrict__ out) {
    __shared__ double sm[1024];
    const int tid = threadIdx.x;
    double acc = 0.0;
    for (int i = tid; i < 2 * NPTS; i += 1024)
        acc += (double)g_dmin[i];
    sm[tid] = acc;
    __syncthreads();
    for (int o = 512; o; o >>= 1) {
        if (tid < o) sm[tid] += sm[tid + o];
        __syncthreads();
    }
    if (tid == 0) out[0] = (float)(sm[0] * (1.0 / (double)NPTS));
}

extern "C" void kernel_launch(void* const* d_in, const int* in_sizes, int n_in,
                              void* d_out, int out_size) {
    const float* p_hat = (const float*)d_in[0];  // [16384,3]
    const float* p     = (const float*)d_in[1];  // [16384,3]
    float* out = (float*)d_out;

    hist_kernel<<<32, 1024>>>(p_hat, p);
    prefix_kernel<<<2, 1024>>>();
    scatter_kernel<<<32, 1024>>>(p_hat, p);
    query_kernel<<<4096, 256>>>();
    reduce_kernel<<<1, 1024>>>(out);
}